// round 1
// baseline (speedup 1.0000x reference)
#include <cuda_runtime.h>
#include <math.h>

// ---------------------------------------------------------------------------
// LocalAttention: B=2, S=2048, E=1024, H=16, D=64, WINDOW=128
//   q/k/v = x@W + b ; banded softmax(q k^T / 32) v ; out = att@Wo + bo
// Round 1: fp32 SIMT with packed fma.rn.f32x2 (Blackwell 2x FFMA path).
// ---------------------------------------------------------------------------

constexpr int BATCH = 2;
constexpr int S_LEN = 2048;
constexpr int EMB   = 1024;
constexpr int HEADS = 16;
constexpr int HDIM  = 64;
constexpr int MTOT  = BATCH * S_LEN;      // 4096 rows
constexpr int QT    = 64;                 // query tile
constexpr int KWIN  = 320;                // 5 x 64 key window per query tile

// scratch (allocation-free: __device__ globals)
__device__ float g_Q[MTOT * EMB];
__device__ float g_K[MTOT * EMB];
__device__ float g_V[MTOT * EMB];
__device__ float g_A[MTOT * EMB];

// ---------------- packed f32x2 helpers ----------------
__device__ __forceinline__ unsigned long long pack2(float lo, float hi) {
    unsigned long long r;
    asm("mov.b64 %0, {%1, %2};" : "=l"(r) : "f"(lo), "f"(hi));
    return r;
}
__device__ __forceinline__ void fma2(unsigned long long& d,
                                     unsigned long long a,
                                     unsigned long long b) {
    asm("fma.rn.f32x2 %0, %1, %2, %3;" : "=l"(d) : "l"(a), "l"(b), "l"(d));
}
__device__ __forceinline__ float2 unpack2(unsigned long long v) {
    float2 f;
    asm("mov.b64 {%0, %1}, %2;" : "=f"(f.x), "=f"(f.y) : "l"(v));
    return f;
}

// ---------------------------------------------------------------------------
// GEMM + bias: C[M,N] = A[M,K] @ W[K,N] + bias[N]
// 128x128 block tile, BK=8, 256 threads, 8x8 per thread (f32x2 packed).
// M,N,K multiples of 128/8 (4096,1024,1024 here).
// ---------------------------------------------------------------------------
__global__ void __launch_bounds__(256, 2)
gemm_bias_kernel(const float* __restrict__ A, const float* __restrict__ W,
                 const float* __restrict__ bias, float* __restrict__ C,
                 int M, int N, int K)
{
    __shared__ float As[8][132];   // transposed A tile, padded vs bank conflicts
    __shared__ float Bs[8][128];

    const int tid  = threadIdx.x;
    const int brow = blockIdx.y;
    const int bcol = blockIdx.x;
    const int trow = tid >> 4;     // 0..15
    const int tcol = tid & 15;     // 0..15

    unsigned long long acc[8][4];
#pragma unroll
    for (int i = 0; i < 8; i++)
#pragma unroll
        for (int j = 0; j < 4; j++) acc[i][j] = 0ull;

    const int arow = tid >> 1;            // 0..127
    const int acg  = (tid & 1) * 4;       // 0 or 4
    const int brw  = tid >> 5;            // 0..7
    const int bcg  = (tid & 31) * 4;      // 0..124

    const float* Aptr = A + (size_t)(brow * 128 + arow) * K + acg;
    const float* Wptr = W + (size_t)brw * N + bcol * 128 + bcg;

    for (int kt = 0; kt < K; kt += 8) {
        float4 av = *(const float4*)(Aptr + kt);
        float4 bv = *(const float4*)(Wptr + (size_t)kt * N);
        __syncthreads();
        As[acg + 0][arow] = av.x;
        As[acg + 1][arow] = av.y;
        As[acg + 2][arow] = av.z;
        As[acg + 3][arow] = av.w;
        *(float4*)&Bs[brw][bcg] = bv;
        __syncthreads();

#pragma unroll
        for (int kk = 0; kk < 8; kk++) {
            float4 a0 = *(const float4*)&As[kk][trow * 8];
            float4 a1 = *(const float4*)&As[kk][trow * 8 + 4];
            const unsigned long long* bp =
                (const unsigned long long*)&Bs[kk][tcol * 8];
            unsigned long long b0 = bp[0], b1 = bp[1], b2 = bp[2], b3 = bp[3];
            unsigned long long ap[8];
            ap[0] = pack2(a0.x, a0.x);
            ap[1] = pack2(a0.y, a0.y);
            ap[2] = pack2(a0.z, a0.z);
            ap[3] = pack2(a0.w, a0.w);
            ap[4] = pack2(a1.x, a1.x);
            ap[5] = pack2(a1.y, a1.y);
            ap[6] = pack2(a1.z, a1.z);
            ap[7] = pack2(a1.w, a1.w);
#pragma unroll
            for (int i = 0; i < 8; i++) {
                fma2(acc[i][0], ap[i], b0);
                fma2(acc[i][1], ap[i], b1);
                fma2(acc[i][2], ap[i], b2);
                fma2(acc[i][3], ap[i], b3);
            }
        }
    }

    const int crow = brow * 128 + trow * 8;
    const int ccol = bcol * 128 + tcol * 8;
    float4 bv0 = *(const float4*)(bias + ccol);
    float4 bv1 = *(const float4*)(bias + ccol + 4);
#pragma unroll
    for (int i = 0; i < 8; i++) {
        float2 x0 = unpack2(acc[i][0]);
        float2 x1 = unpack2(acc[i][1]);
        float2 x2 = unpack2(acc[i][2]);
        float2 x3 = unpack2(acc[i][3]);
        float4 o0 = make_float4(x0.x + bv0.x, x0.y + bv0.y,
                                x1.x + bv0.z, x1.y + bv0.w);
        float4 o1 = make_float4(x2.x + bv1.x, x2.y + bv1.y,
                                x3.x + bv1.z, x3.y + bv1.w);
        *(float4*)(C + (size_t)(crow + i) * N + ccol)     = o0;
        *(float4*)(C + (size_t)(crow + i) * N + ccol + 4) = o1;
    }
}

// ---------------------------------------------------------------------------
// Banded attention. One CTA per (64-query tile, b*h). 256 threads.
// SMEM: Qs[64][68] (d-major), KVs[64][68], Ss[64][324], rowsum[64]
// ---------------------------------------------------------------------------
__global__ void __launch_bounds__(256, 1)
attn_kernel(const float* __restrict__ Q, const float* __restrict__ K,
            const float* __restrict__ V, float* __restrict__ O)
{
    extern __shared__ float sm[];
    float (*Qs)[68]  = (float(*)[68])sm;                    // [d][q]
    float (*KVs)[68] = (float(*)[68])(sm + 64 * 68);        // phase1 [d][k], phase3 [k][d]
    float (*Ss)[324] = (float(*)[324])(sm + 2 * 64 * 68);   // [q][k]
    float* rowsum    = sm + 2 * 64 * 68 + 64 * 324;

    const int tid = threadIdx.x;
    const int q0  = blockIdx.x * QT;
    const int bh  = blockIdx.y;
    const int b   = bh >> 4;
    const int h   = bh & 15;
    const size_t base = ((size_t)b * S_LEN) * EMB + (size_t)h * HDIM;

    // load Q tile, transposed to Qs[d][q]
#pragma unroll
    for (int r = 0; r < 4; r++) {
        int idx = tid + 256 * r;       // float4 index 0..1023
        int row = idx >> 4;            // q in tile
        int c4  = idx & 15;
        float4 v = *(const float4*)(Q + base + (size_t)(q0 + row) * EMB + c4 * 4);
        Qs[c4 * 4 + 0][row] = v.x;
        Qs[c4 * 4 + 1][row] = v.y;
        Qs[c4 * 4 + 2][row] = v.z;
        Qs[c4 * 4 + 3][row] = v.w;
    }

    const int trow = tid >> 4;   // 0..15
    const int tcol = tid & 15;   // 0..15
    const float inv_scale = 0.03125f;   // 1/sqrt(1024)

    // -------- phase 1: S = Q K^T over 5 key chunks --------
    for (int c = 0; c < 5; c++) {
        __syncthreads();
#pragma unroll
        for (int r = 0; r < 4; r++) {
            int idx = tid + 256 * r;
            int row = idx >> 4;
            int c4  = idx & 15;
            int kidx = q0 - 128 + c * 64 + row;
            float4 v = make_float4(0.f, 0.f, 0.f, 0.f);
            if (kidx >= 0 && kidx < S_LEN)
                v = *(const float4*)(K + base + (size_t)kidx * EMB + c4 * 4);
            KVs[c4 * 4 + 0][row] = v.x;     // transposed: [d][k]
            KVs[c4 * 4 + 1][row] = v.y;
            KVs[c4 * 4 + 2][row] = v.z;
            KVs[c4 * 4 + 3][row] = v.w;
        }
        __syncthreads();

        unsigned long long acc[4][2];
#pragma unroll
        for (int i = 0; i < 4; i++) { acc[i][0] = 0ull; acc[i][1] = 0ull; }

#pragma unroll 4
        for (int d = 0; d < 64; d++) {
            const unsigned long long* kp =
                (const unsigned long long*)&KVs[d][tcol * 4];
            unsigned long long b0 = kp[0], b1 = kp[1];
            float4 aq = *(const float4*)&Qs[d][trow * 4];
            unsigned long long a0 = pack2(aq.x, aq.x);
            unsigned long long a1 = pack2(aq.y, aq.y);
            unsigned long long a2 = pack2(aq.z, aq.z);
            unsigned long long a3 = pack2(aq.w, aq.w);
            fma2(acc[0][0], a0, b0); fma2(acc[0][1], a0, b1);
            fma2(acc[1][0], a1, b0); fma2(acc[1][1], a1, b1);
            fma2(acc[2][0], a2, b0); fma2(acc[2][1], a2, b1);
            fma2(acc[3][0], a3, b0); fma2(acc[3][1], a3, b1);
        }

#pragma unroll
        for (int i = 0; i < 4; i++) {
            int qi = q0 + trow * 4 + i;
            float2 p01 = unpack2(acc[i][0]);
            float2 p23 = unpack2(acc[i][1]);
            float sv[4] = {p01.x, p01.y, p23.x, p23.y};
#pragma unroll
            for (int j = 0; j < 4; j++) {
                int kidx = q0 - 128 + c * 64 + tcol * 4 + j;
                int diff = kidx - qi;
                bool ok = (kidx >= 0) && (kidx < S_LEN) &&
                          (diff <= 128) && (diff >= -128);
                Ss[trow * 4 + i][c * 64 + tcol * 4 + j] =
                    ok ? sv[j] * inv_scale : -1e30f;
            }
        }
    }
    __syncthreads();

    // -------- phase 2: row softmax (4 threads per row) --------
    {
        int row = tid >> 2;
        int l   = tid & 3;
        float m = -1e30f;
        for (int cc = l; cc < KWIN; cc += 4) m = fmaxf(m, Ss[row][cc]);
        m = fmaxf(m, __shfl_xor_sync(0xFFFFFFFF, m, 1));
        m = fmaxf(m, __shfl_xor_sync(0xFFFFFFFF, m, 2));
        float s = 0.f;
        for (int cc = l; cc < KWIN; cc += 4) {
            float p = __expf(Ss[row][cc] - m);
            Ss[row][cc] = p;
            s += p;
        }
        s += __shfl_xor_sync(0xFFFFFFFF, s, 1);
        s += __shfl_xor_sync(0xFFFFFFFF, s, 2);
        if (l == 0) rowsum[row] = s;
    }

    // -------- phase 3: O = P V over 5 key chunks --------
    unsigned long long oacc[4][2];
#pragma unroll
    for (int i = 0; i < 4; i++) { oacc[i][0] = 0ull; oacc[i][1] = 0ull; }

    for (int c = 0; c < 5; c++) {
        __syncthreads();
#pragma unroll
        for (int r = 0; r < 4; r++) {
            int idx = tid + 256 * r;
            int row = idx >> 4;
            int c4  = idx & 15;
            int kidx = q0 - 128 + c * 64 + row;
            float4 v = make_float4(0.f, 0.f, 0.f, 0.f);
            if (kidx >= 0 && kidx < S_LEN)
                v = *(const float4*)(V + base + (size_t)kidx * EMB + c4 * 4);
            *(float4*)&KVs[row][c4 * 4] = v;    // direct layout [k][d]
        }
        __syncthreads();

#pragma unroll 4
        for (int kk = 0; kk < 64; kk++) {
            const unsigned long long* vp =
                (const unsigned long long*)&KVs[kk][tcol * 4];
            unsigned long long b0 = vp[0], b1 = vp[1];
            float p0 = Ss[trow * 4 + 0][c * 64 + kk];
            float p1 = Ss[trow * 4 + 1][c * 64 + kk];
            float p2 = Ss[trow * 4 + 2][c * 64 + kk];
            float p3 = Ss[trow * 4 + 3][c * 64 + kk];
            unsigned long long a0 = pack2(p0, p0);
            unsigned long long a1 = pack2(p1, p1);
            unsigned long long a2 = pack2(p2, p2);
            unsigned long long a3 = pack2(p3, p3);
            fma2(oacc[0][0], a0, b0); fma2(oacc[0][1], a0, b1);
            fma2(oacc[1][0], a1, b0); fma2(oacc[1][1], a1, b1);
            fma2(oacc[2][0], a2, b0); fma2(oacc[2][1], a2, b1);
            fma2(oacc[3][0], a3, b0); fma2(oacc[3][1], a3, b1);
        }
    }

    // -------- epilogue: normalize + store --------
#pragma unroll
    for (int i = 0; i < 4; i++) {
        int qi = trow * 4 + i;
        float r = 1.0f / rowsum[qi];
        float2 o01 = unpack2(oacc[i][0]);
        float2 o23 = unpack2(oacc[i][1]);
        float4 ov = make_float4(o01.x * r, o01.y * r, o23.x * r, o23.y * r);
        *(float4*)(O + base + (size_t)(q0 + qi) * EMB + tcol * 4) = ov;
    }
}

// ---------------------------------------------------------------------------
extern "C" void kernel_launch(void* const* d_in, const int* in_sizes, int n_in,
                              void* d_out, int out_size)
{
    const float* x  = (const float*)d_in[0];
    const float* Wq = (const float*)d_in[1];
    const float* bq = (const float*)d_in[2];
    const float* Wk = (const float*)d_in[3];
    const float* bk = (const float*)d_in[4];
    const float* Wv = (const float*)d_in[5];
    const float* bv = (const float*)d_in[6];
    const float* Wo = (const float*)d_in[7];
    const float* bo = (const float*)d_in[8];
    float* out = (float*)d_out;

    float *pQ, *pK, *pV, *pA;
    cudaGetSymbolAddress((void**)&pQ, g_Q);
    cudaGetSymbolAddress((void**)&pK, g_K);
    cudaGetSymbolAddress((void**)&pV, g_V);
    cudaGetSymbolAddress((void**)&pA, g_A);

    dim3 ggrid(EMB / 128, MTOT / 128);   // (8, 32)
    gemm_bias_kernel<<<ggrid, 256>>>(x, Wq, bq, pQ, MTOT, EMB, EMB);
    gemm_bias_kernel<<<ggrid, 256>>>(x, Wk, bk, pK, MTOT, EMB, EMB);
    gemm_bias_kernel<<<ggrid, 256>>>(x, Wv, bv, pV, MTOT, EMB, EMB);

    const int smem_att = (2 * 64 * 68 + 64 * 324 + 64) * (int)sizeof(float);
    cudaFuncSetAttribute(attn_kernel,
                         cudaFuncAttributeMaxDynamicSharedMemorySize, smem_att);
    dim3 agrid(S_LEN / QT, BATCH * HEADS);   // (32, 32)
    attn_kernel<<<agrid, 256, smem_att>>>(pQ, pK, pV, pA);

    gemm_bias_kernel<<<ggrid, 256>>>(pA, Wo, bo, out, MTOT, EMB, EMB);
}

// round 4
// speedup vs baseline: 2.0111x; 2.0111x over previous
#include <cuda_runtime.h>
#include <cuda_bf16.h>
#include <cstdint>
#include <math.h>

// ---------------------------------------------------------------------------
// LocalAttention: B=2, S=2048, E=1024, H=16, D=64, WINDOW=128
// Round 4: mma.sync bf16 (3-term split) GEMMs. Fix vs R3: B-fragment n-pair
//          stride is 16 rows = 2048 bytes (was 4096 -> OOB smem read).
// ---------------------------------------------------------------------------

constexpr int BATCH = 2;
constexpr int S_LEN = 2048;
constexpr int EMB   = 1024;
constexpr int HDIM  = 64;
constexpr int MTOT  = BATCH * S_LEN;      // 4096 rows
constexpr int QT    = 64;
constexpr int KWIN  = 320;

// fp32 scratch
__device__ float g_Q[MTOT * EMB];
__device__ float g_K[MTOT * EMB];
__device__ float g_V[MTOT * EMB];
__device__ float g_A[MTOT * EMB];
// bf16 split scratch
__device__ __nv_bfloat16 g_Xhi[MTOT * EMB];
__device__ __nv_bfloat16 g_Xlo[MTOT * EMB];
__device__ __nv_bfloat16 g_Ahi[MTOT * EMB];
__device__ __nv_bfloat16 g_Alo[MTOT * EMB];
__device__ __nv_bfloat16 g_Wth[4 * EMB * EMB];   // W^T hi (4 weights)
__device__ __nv_bfloat16 g_Wtl[4 * EMB * EMB];   // W^T lo

#define SMEM_SWIZZLE_128B(o) ((o) ^ (((o) >> 3) & 0x70))

__device__ __forceinline__ uint32_t smem_to_u32(const void* p) {
    uint32_t a;
    asm("{ .reg .u64 t; cvta.to.shared.u64 t, %1; cvt.u32.u64 %0, t; }"
        : "=r"(a) : "l"(p));
    return a;
}
__device__ __forceinline__ void cp_async16(uint32_t dst, const void* src) {
    asm volatile("cp.async.cg.shared.global [%0], [%1], 16;"
                 :: "r"(dst), "l"(src) : "memory");
}
__device__ __forceinline__ void cp_commit() {
    asm volatile("cp.async.commit_group;" ::: "memory");
}
__device__ __forceinline__ void cp_wait1() {
    asm volatile("cp.async.wait_group 1;" ::: "memory");
}
__device__ __forceinline__ void cp_wait0() {
    asm volatile("cp.async.wait_group 0;" ::: "memory");
}
__device__ __forceinline__ void ldsm_x4(uint32_t& r0, uint32_t& r1,
                                        uint32_t& r2, uint32_t& r3,
                                        uint32_t addr) {
    asm volatile("ldmatrix.sync.aligned.m8n8.x4.shared.b16 {%0,%1,%2,%3}, [%4];"
                 : "=r"(r0), "=r"(r1), "=r"(r2), "=r"(r3) : "r"(addr));
}
__device__ __forceinline__ void mma_bf16(float* c, const uint32_t* a,
                                         const uint32_t* b) {
    asm volatile(
        "mma.sync.aligned.m16n8k16.row.col.f32.bf16.bf16.f32 "
        "{%0,%1,%2,%3}, {%4,%5,%6,%7}, {%8,%9}, {%0,%1,%2,%3};"
        : "+f"(c[0]), "+f"(c[1]), "+f"(c[2]), "+f"(c[3])
        : "r"(a[0]), "r"(a[1]), "r"(a[2]), "r"(a[3]), "r"(b[0]), "r"(b[1]));
}

// ======================= conversion kernels ================================
__global__ void split_kernel(const float4* __restrict__ src,
                             uint2* __restrict__ hi, uint2* __restrict__ lo,
                             int n4)
{
    int i = blockIdx.x * blockDim.x + threadIdx.x;
    if (i >= n4) return;
    float4 v = src[i];
    float f[4] = {v.x, v.y, v.z, v.w};
    unsigned short hb[4], lb[4];
#pragma unroll
    for (int j = 0; j < 4; j++) {
        __nv_bfloat16 h = __float2bfloat16(f[j]);
        __nv_bfloat16 l = __float2bfloat16(f[j] - __bfloat162float(h));
        hb[j] = __bfloat16_as_ushort(h);
        lb[j] = __bfloat16_as_ushort(l);
    }
    hi[i] = make_uint2((uint32_t)hb[0] | ((uint32_t)hb[1] << 16),
                       (uint32_t)hb[2] | ((uint32_t)hb[3] << 16));
    lo[i] = make_uint2((uint32_t)lb[0] | ((uint32_t)lb[1] << 16),
                       (uint32_t)lb[2] | ((uint32_t)lb[3] << 16));
}

// W[k][n] (1024x1024) -> Th[n][k], Tl[n][k] bf16
__global__ void transpose_split_kernel(const float* __restrict__ W,
                                       __nv_bfloat16* __restrict__ Th,
                                       __nv_bfloat16* __restrict__ Tl)
{
    __shared__ float t[32][33];
    int nx = blockIdx.x * 32, ky = blockIdx.y * 32;
    int tx = threadIdx.x, ty = threadIdx.y;
#pragma unroll
    for (int i = 0; i < 32; i += 8)
        t[ty + i][tx] = W[(size_t)(ky + ty + i) * EMB + nx + tx];
    __syncthreads();
#pragma unroll
    for (int i = 0; i < 32; i += 8) {
        float v = t[tx][ty + i];
        __nv_bfloat16 h = __float2bfloat16(v);
        __nv_bfloat16 l = __float2bfloat16(v - __bfloat162float(h));
        size_t o = (size_t)(nx + ty + i) * EMB + ky + tx;
        Th[o] = h;
        Tl[o] = l;
    }
}

// ======================= mma.sync GEMM =====================================
// C[M,1024] = A[M,1024] @ W[1024,1024] + bias, 3-term bf16 split.
// CTA tile 128x128, BK=64, 8 warps (warp tile 64x32), cp.async double buffer.
constexpr int GSM_A0 = 0;
constexpr int GSM_B0 = 16384;
constexpr int GSM_A1 = 32768;
constexpr int GSM_B1 = 49152;
constexpr int GSM_TOTAL = 65536;

__device__ __forceinline__ void gemm_issue_chunk(
    const __nv_bfloat16* __restrict__ Asrc,
    const __nv_bfloat16* __restrict__ Bsrc,
    uint32_t smem_base, uint32_t offA, uint32_t offB, int tid)
{
#pragma unroll
    for (int i = 0; i < 4; i++) {
        int cidx = tid + 256 * i;          // 0..1023 16B chunks
        int r  = cidx >> 3;                // row 0..127
        int cb = cidx & 7;                 // 16B chunk in 128B row
        uint32_t sw = SMEM_SWIZZLE_128B((uint32_t)(r * 128 + cb * 16));
        cp_async16(smem_base + offA + sw, Asrc + (size_t)r * EMB + cb * 8);
        cp_async16(smem_base + offB + sw, Bsrc + (size_t)r * EMB + cb * 8);
    }
    cp_commit();
}

__global__ void __launch_bounds__(256, 2)
tc_gemm_kernel(const __nv_bfloat16* __restrict__ Ah,
               const __nv_bfloat16* __restrict__ Al,
               const __nv_bfloat16* __restrict__ Bh,
               const __nv_bfloat16* __restrict__ Bl,
               const float* __restrict__ bias, float* __restrict__ C)
{
    extern __shared__ char smem[];
    const uint32_t smem_base = smem_to_u32(smem);
    const int tid  = threadIdx.x;
    const int w    = tid >> 5;
    const int lane = tid & 31;
    const int n0 = blockIdx.x * 128;
    const int m0 = blockIdx.y * 128;

    const int wm = (w & 1) * 64;        // warp m offset in tile
    const int wn = (w >> 1) * 32;       // warp n offset in tile

    const __nv_bfloat16* Ap[3] = {Ah, Ah, Al};
    const __nv_bfloat16* Bp[3] = {Bh, Bl, Bh};
    const uint32_t offA[2] = {GSM_A0, GSM_A1};
    const uint32_t offB[2] = {GSM_B0, GSM_B1};

    float acc[4][4][4];
#pragma unroll
    for (int i = 0; i < 4; i++)
#pragma unroll
        for (int j = 0; j < 4; j++)
#pragma unroll
            for (int k = 0; k < 4; k++) acc[i][j][k] = 0.f;

    // lane-fixed parts of ldmatrix addresses (pre-swizzle)
    const uint32_t aRowOff =
        (uint32_t)((wm + (lane & 15)) * 128) + (uint32_t)((lane >> 4) * 16);
    const uint32_t bRowOff =
        (uint32_t)((wn + ((lane >> 4) << 3) + (lane & 7)) * 128) +
        (uint32_t)(((lane >> 3) & 1) * 16);

    // prologue: chunk 0
    gemm_issue_chunk(Ap[0] + (size_t)m0 * EMB, Bp[0] + (size_t)n0 * EMB,
                     smem_base, offA[0], offB[0], tid);

    for (int c = 0; c < 48; c++) {
        const int buf = c & 1;
        if (c + 1 < 48) {
            const int pass = (c + 1) >> 4;
            const int kc   = ((c + 1) & 15) * 64;
            gemm_issue_chunk(Ap[pass] + (size_t)m0 * EMB + kc,
                             Bp[pass] + (size_t)n0 * EMB + kc,
                             smem_base, offA[buf ^ 1], offB[buf ^ 1], tid);
            cp_wait1();
        } else {
            cp_wait0();
        }
        __syncthreads();

        const uint32_t abase = smem_base + offA[buf];
        const uint32_t bbase = smem_base + offB[buf];
#pragma unroll
        for (int ks = 0; ks < 4; ks++) {
            const uint32_t kb = ks * 32;
            uint32_t bfrag[4][2];
#pragma unroll
            for (int p = 0; p < 2; p++) {
                // p selects 16 n-rows = 16 * 128 bytes = 2048 (R3 bug: 4096)
                uint32_t off = bRowOff + p * 2048 + kb;
                uint32_t sw  = SMEM_SWIZZLE_128B(off);
                ldsm_x4(bfrag[2 * p][0], bfrag[2 * p][1],
                        bfrag[2 * p + 1][0], bfrag[2 * p + 1][1], bbase + sw);
            }
            uint32_t afrag[4][4];
#pragma unroll
            for (int mt = 0; mt < 4; mt++) {
                uint32_t off = aRowOff + mt * 2048 + kb;
                uint32_t sw  = SMEM_SWIZZLE_128B(off);
                ldsm_x4(afrag[mt][0], afrag[mt][1], afrag[mt][2], afrag[mt][3],
                        abase + sw);
            }
#pragma unroll
            for (int mt = 0; mt < 4; mt++)
#pragma unroll
                for (int nt = 0; nt < 4; nt++)
                    mma_bf16(acc[mt][nt], afrag[mt], bfrag[nt]);
        }
        __syncthreads();
    }

    // epilogue: direct fp32 stores + bias
    const int rbase = m0 + wm + (lane >> 2);
    const int cbase = n0 + wn + (lane & 3) * 2;
#pragma unroll
    for (int mt = 0; mt < 4; mt++) {
#pragma unroll
        for (int nt = 0; nt < 4; nt++) {
            const int r = rbase + mt * 16;
            const int cc = cbase + nt * 8;
            float2 b2 = *(const float2*)(bias + cc);
            float2 o0 = make_float2(acc[mt][nt][0] + b2.x,
                                    acc[mt][nt][1] + b2.y);
            float2 o1 = make_float2(acc[mt][nt][2] + b2.x,
                                    acc[mt][nt][3] + b2.y);
            *(float2*)(C + (size_t)r * EMB + cc)       = o0;
            *(float2*)(C + (size_t)(r + 8) * EMB + cc) = o1;
        }
    }
}

// ======================= banded attention (R1, unchanged) ==================
__device__ __forceinline__ unsigned long long pack2(float lo, float hi) {
    unsigned long long r;
    asm("mov.b64 %0, {%1, %2};" : "=l"(r) : "f"(lo), "f"(hi));
    return r;
}
__device__ __forceinline__ void fma2(unsigned long long& d,
                                     unsigned long long a,
                                     unsigned long long b) {
    asm("fma.rn.f32x2 %0, %1, %2, %3;" : "=l"(d) : "l"(a), "l"(b), "l"(d));
}
__device__ __forceinline__ float2 unpack2(unsigned long long v) {
    float2 f;
    asm("mov.b64 {%0, %1}, %2;" : "=f"(f.x), "=f"(f.y) : "l"(v));
    return f;
}

__global__ void __launch_bounds__(256, 1)
attn_kernel(const float* __restrict__ Q, const float* __restrict__ K,
            const float* __restrict__ V, float* __restrict__ O)
{
    extern __shared__ float sm[];
    float (*Qs)[68]  = (float(*)[68])sm;
    float (*KVs)[68] = (float(*)[68])(sm + 64 * 68);
    float (*Ss)[324] = (float(*)[324])(sm + 2 * 64 * 68);
    float* rowsum    = sm + 2 * 64 * 68 + 64 * 324;

    const int tid = threadIdx.x;
    const int q0  = blockIdx.x * QT;
    const int bh  = blockIdx.y;
    const int b   = bh >> 4;
    const int h   = bh & 15;
    const size_t base = ((size_t)b * S_LEN) * EMB + (size_t)h * HDIM;

#pragma unroll
    for (int r = 0; r < 4; r++) {
        int idx = tid + 256 * r;
        int row = idx >> 4;
        int c4  = idx & 15;
        float4 v = *(const float4*)(Q + base + (size_t)(q0 + row) * EMB + c4 * 4);
        Qs[c4 * 4 + 0][row] = v.x;
        Qs[c4 * 4 + 1][row] = v.y;
        Qs[c4 * 4 + 2][row] = v.z;
        Qs[c4 * 4 + 3][row] = v.w;
    }

    const int trow = tid >> 4;
    const int tcol = tid & 15;
    const float inv_scale = 0.03125f;

    for (int c = 0; c < 5; c++) {
        __syncthreads();
#pragma unroll
        for (int r = 0; r < 4; r++) {
            int idx = tid + 256 * r;
            int row = idx >> 4;
            int c4  = idx & 15;
            int kidx = q0 - 128 + c * 64 + row;
            float4 v = make_float4(0.f, 0.f, 0.f, 0.f);
            if (kidx >= 0 && kidx < S_LEN)
                v = *(const float4*)(K + base + (size_t)kidx * EMB + c4 * 4);
            KVs[c4 * 4 + 0][row] = v.x;
            KVs[c4 * 4 + 1][row] = v.y;
            KVs[c4 * 4 + 2][row] = v.z;
            KVs[c4 * 4 + 3][row] = v.w;
        }
        __syncthreads();

        unsigned long long acc[4][2];
#pragma unroll
        for (int i = 0; i < 4; i++) { acc[i][0] = 0ull; acc[i][1] = 0ull; }

#pragma unroll 4
        for (int d = 0; d < 64; d++) {
            const unsigned long long* kp =
                (const unsigned long long*)&KVs[d][tcol * 4];
            unsigned long long b0 = kp[0], b1 = kp[1];
            float4 aq = *(const float4*)&Qs[d][trow * 4];
            unsigned long long a0 = pack2(aq.x, aq.x);
            unsigned long long a1 = pack2(aq.y, aq.y);
            unsigned long long a2 = pack2(aq.z, aq.z);
            unsigned long long a3 = pack2(aq.w, aq.w);
            fma2(acc[0][0], a0, b0); fma2(acc[0][1], a0, b1);
            fma2(acc[1][0], a1, b0); fma2(acc[1][1], a1, b1);
            fma2(acc[2][0], a2, b0); fma2(acc[2][1], a2, b1);
            fma2(acc[3][0], a3, b0); fma2(acc[3][1], a3, b1);
        }

#pragma unroll
        for (int i = 0; i < 4; i++) {
            int qi = q0 + trow * 4 + i;
            float2 p01 = unpack2(acc[i][0]);
            float2 p23 = unpack2(acc[i][1]);
            float sv[4] = {p01.x, p01.y, p23.x, p23.y};
#pragma unroll
            for (int j = 0; j < 4; j++) {
                int kidx = q0 - 128 + c * 64 + tcol * 4 + j;
                int diff = kidx - qi;
                bool ok = (kidx >= 0) && (kidx < S_LEN) &&
                          (diff <= 128) && (diff >= -128);
                Ss[trow * 4 + i][c * 64 + tcol * 4 + j] =
                    ok ? sv[j] * inv_scale : -1e30f;
            }
        }
    }
    __syncthreads();

    {
        int row = tid >> 2;
        int l   = tid & 3;
        float m = -1e30f;
        for (int cc = l; cc < KWIN; cc += 4) m = fmaxf(m, Ss[row][cc]);
        m = fmaxf(m, __shfl_xor_sync(0xFFFFFFFF, m, 1));
        m = fmaxf(m, __shfl_xor_sync(0xFFFFFFFF, m, 2));
        float s = 0.f;
        for (int cc = l; cc < KWIN; cc += 4) {
            float p = __expf(Ss[row][cc] - m);
            Ss[row][cc] = p;
            s += p;
        }
        s += __shfl_xor_sync(0xFFFFFFFF, s, 1);
        s += __shfl_xor_sync(0xFFFFFFFF, s, 2);
        if (l == 0) rowsum[row] = s;
    }

    unsigned long long oacc[4][2];
#pragma unroll
    for (int i = 0; i < 4; i++) { oacc[i][0] = 0ull; oacc[i][1] = 0ull; }

    for (int c = 0; c < 5; c++) {
        __syncthreads();
#pragma unroll
        for (int r = 0; r < 4; r++) {
            int idx = tid + 256 * r;
            int row = idx >> 4;
            int c4  = idx & 15;
            int kidx = q0 - 128 + c * 64 + row;
            float4 v = make_float4(0.f, 0.f, 0.f, 0.f);
            if (kidx >= 0 && kidx < S_LEN)
                v = *(const float4*)(V + base + (size_t)kidx * EMB + c4 * 4);
            *(float4*)&KVs[row][c4 * 4] = v;
        }
        __syncthreads();

#pragma unroll 4
        for (int kk = 0; kk < 64; kk++) {
            const unsigned long long* vp =
                (const unsigned long long*)&KVs[kk][tcol * 4];
            unsigned long long b0 = vp[0], b1 = vp[1];
            float p0 = Ss[trow * 4 + 0][c * 64 + kk];
            float p1 = Ss[trow * 4 + 1][c * 64 + kk];
            float p2 = Ss[trow * 4 + 2][c * 64 + kk];
            float p3 = Ss[trow * 4 + 3][c * 64 + kk];
            unsigned long long a0 = pack2(p0, p0);
            unsigned long long a1 = pack2(p1, p1);
            unsigned long long a2 = pack2(p2, p2);
            unsigned long long a3 = pack2(p3, p3);
            fma2(oacc[0][0], a0, b0); fma2(oacc[0][1], a0, b1);
            fma2(oacc[1][0], a1, b0); fma2(oacc[1][1], a1, b1);
            fma2(oacc[2][0], a2, b0); fma2(oacc[2][1], a2, b1);
            fma2(oacc[3][0], a3, b0); fma2(oacc[3][1], a3, b1);
        }
    }

#pragma unroll
    for (int i = 0; i < 4; i++) {
        int qi = trow * 4 + i;
        float r = 1.0f / rowsum[qi];
        float2 o01 = unpack2(oacc[i][0]);
        float2 o23 = unpack2(oacc[i][1]);
        float4 ov = make_float4(o01.x * r, o01.y * r, o23.x * r, o23.y * r);
        *(float4*)(O + base + (size_t)(q0 + qi) * EMB + tcol * 4) = ov;
    }
}

// ===========================================================================
extern "C" void kernel_launch(void* const* d_in, const int* in_sizes, int n_in,
                              void* d_out, int out_size)
{
    const float* x  = (const float*)d_in[0];
    const float* Wq = (const float*)d_in[1];
    const float* bq = (const float*)d_in[2];
    const float* Wk = (const float*)d_in[3];
    const float* bk = (const float*)d_in[4];
    const float* Wv = (const float*)d_in[5];
    const float* bv = (const float*)d_in[6];
    const float* Wo = (const float*)d_in[7];
    const float* bo = (const float*)d_in[8];
    float* out = (float*)d_out;

    float *pQ, *pK, *pV, *pA;
    cudaGetSymbolAddress((void**)&pQ, g_Q);
    cudaGetSymbolAddress((void**)&pK, g_K);
    cudaGetSymbolAddress((void**)&pV, g_V);
    cudaGetSymbolAddress((void**)&pA, g_A);
    __nv_bfloat16 *pXh, *pXl, *pAh, *pAl, *pWth, *pWtl;
    cudaGetSymbolAddress((void**)&pXh, g_Xhi);
    cudaGetSymbolAddress((void**)&pXl, g_Xlo);
    cudaGetSymbolAddress((void**)&pAh, g_Ahi);
    cudaGetSymbolAddress((void**)&pAl, g_Alo);
    cudaGetSymbolAddress((void**)&pWth, g_Wth);
    cudaGetSymbolAddress((void**)&pWtl, g_Wtl);

    cudaFuncSetAttribute(tc_gemm_kernel,
                         cudaFuncAttributeMaxDynamicSharedMemorySize, GSM_TOTAL);
    const int smem_att = (2 * 64 * 68 + 64 * 324 + 64) * (int)sizeof(float);
    cudaFuncSetAttribute(attn_kernel,
                         cudaFuncAttributeMaxDynamicSharedMemorySize, smem_att);

    const int n4 = MTOT * EMB / 4;
    split_kernel<<<(n4 + 255) / 256, 256>>>((const float4*)x,
                                            (uint2*)pXh, (uint2*)pXl, n4);
    dim3 tgrid(EMB / 32, EMB / 32);
    dim3 tblk(32, 8);
    transpose_split_kernel<<<tgrid, tblk>>>(Wq, pWth + 0ull * EMB * EMB,
                                            pWtl + 0ull * EMB * EMB);
    transpose_split_kernel<<<tgrid, tblk>>>(Wk, pWth + 1ull * EMB * EMB,
                                            pWtl + 1ull * EMB * EMB);
    transpose_split_kernel<<<tgrid, tblk>>>(Wv, pWth + 2ull * EMB * EMB,
                                            pWtl + 2ull * EMB * EMB);
    transpose_split_kernel<<<tgrid, tblk>>>(Wo, pWth + 3ull * EMB * EMB,
                                            pWtl + 3ull * EMB * EMB);

    dim3 ggrid(EMB / 128, MTOT / 128);   // (8, 32)
    tc_gemm_kernel<<<ggrid, 256, GSM_TOTAL>>>(pXh, pXl,
        pWth + 0ull * EMB * EMB, pWtl + 0ull * EMB * EMB, bq, pQ);
    tc_gemm_kernel<<<ggrid, 256, GSM_TOTAL>>>(pXh, pXl,
        pWth + 1ull * EMB * EMB, pWtl + 1ull * EMB * EMB, bk, pK);
    tc_gemm_kernel<<<ggrid, 256, GSM_TOTAL>>>(pXh, pXl,
        pWth + 2ull * EMB * EMB, pWtl + 2ull * EMB * EMB, bv, pV);

    dim3 agrid(S_LEN / QT, BATCH * 16);
    attn_kernel<<<agrid, 256, smem_att>>>(pQ, pK, pV, pA);

    split_kernel<<<(n4 + 255) / 256, 256>>>((const float4*)pA,
                                            (uint2*)pAh, (uint2*)pAl, n4);
    tc_gemm_kernel<<<ggrid, 256, GSM_TOTAL>>>(pAh, pAl,
        pWth + 3ull * EMB * EMB, pWtl + 3ull * EMB * EMB, bo, out);
}

// round 5
// speedup vs baseline: 2.1888x; 1.0884x over previous
#include <cuda_runtime.h>
#include <cuda_bf16.h>
#include <cstdint>
#include <math.h>

// ---------------------------------------------------------------------------
// LocalAttention: B=2, S=2048, E=1024, H=16, D=64, WINDOW=128
// Round 5: mma.sync everywhere. GEMMs emit bf16 hi/lo directly; tensor-core
//          banded attention (3-term split QK^T and PV); fused transposes.
// ---------------------------------------------------------------------------

constexpr int BATCH = 2;
constexpr int S_LEN = 2048;
constexpr int EMB   = 1024;
constexpr int MTOT  = BATCH * S_LEN;      // 4096 rows
constexpr int QT    = 64;
constexpr int KWIN  = 320;

// bf16 split buffers
__device__ __nv_bfloat16 g_Xhi[MTOT * EMB];
__device__ __nv_bfloat16 g_Xlo[MTOT * EMB];
__device__ __nv_bfloat16 g_Qhi[MTOT * EMB];
__device__ __nv_bfloat16 g_Qlo[MTOT * EMB];
__device__ __nv_bfloat16 g_Khi[MTOT * EMB];
__device__ __nv_bfloat16 g_Klo[MTOT * EMB];
__device__ __nv_bfloat16 g_Vhi[MTOT * EMB];
__device__ __nv_bfloat16 g_Vlo[MTOT * EMB];
__device__ __nv_bfloat16 g_Ahi[MTOT * EMB];
__device__ __nv_bfloat16 g_Alo[MTOT * EMB];
__device__ __nv_bfloat16 g_Wth[4 * EMB * EMB];   // W^T hi
__device__ __nv_bfloat16 g_Wtl[4 * EMB * EMB];   // W^T lo

#define SMEM_SWIZZLE_128B(o) ((o) ^ (((o) >> 3) & 0x70))

__device__ __forceinline__ uint32_t smem_to_u32(const void* p) {
    uint32_t a;
    asm("{ .reg .u64 t; cvta.to.shared.u64 t, %1; cvt.u32.u64 %0, t; }"
        : "=r"(a) : "l"(p));
    return a;
}
__device__ __forceinline__ void cp_async16(uint32_t dst, const void* src) {
    asm volatile("cp.async.cg.shared.global [%0], [%1], 16;"
                 :: "r"(dst), "l"(src) : "memory");
}
__device__ __forceinline__ void cp_commit() {
    asm volatile("cp.async.commit_group;" ::: "memory");
}
__device__ __forceinline__ void cp_wait1() {
    asm volatile("cp.async.wait_group 1;" ::: "memory");
}
__device__ __forceinline__ void cp_wait0() {
    asm volatile("cp.async.wait_group 0;" ::: "memory");
}
__device__ __forceinline__ void ldsm_x4(uint32_t& r0, uint32_t& r1,
                                        uint32_t& r2, uint32_t& r3,
                                        uint32_t addr) {
    asm volatile("ldmatrix.sync.aligned.m8n8.x4.shared.b16 {%0,%1,%2,%3}, [%4];"
                 : "=r"(r0), "=r"(r1), "=r"(r2), "=r"(r3) : "r"(addr));
}
__device__ __forceinline__ void mma_bf16(float* c, const uint32_t* a,
                                         const uint32_t* b) {
    asm volatile(
        "mma.sync.aligned.m16n8k16.row.col.f32.bf16.bf16.f32 "
        "{%0,%1,%2,%3}, {%4,%5,%6,%7}, {%8,%9}, {%0,%1,%2,%3};"
        : "+f"(c[0]), "+f"(c[1]), "+f"(c[2]), "+f"(c[3])
        : "r"(a[0]), "r"(a[1]), "r"(a[2]), "r"(a[3]), "r"(b[0]), "r"(b[1]));
}
__device__ __forceinline__ uint32_t pack_bf16x2(__nv_bfloat16 lo,
                                                __nv_bfloat16 hi) {
    return (uint32_t)__bfloat16_as_ushort(lo) |
           ((uint32_t)__bfloat16_as_ushort(hi) << 16);
}

// ======================= conversion kernels ================================
__global__ void split_kernel(const float4* __restrict__ src,
                             uint2* __restrict__ hi, uint2* __restrict__ lo,
                             int n4)
{
    int i = blockIdx.x * blockDim.x + threadIdx.x;
    if (i >= n4) return;
    float4 v = src[i];
    float f[4] = {v.x, v.y, v.z, v.w};
    unsigned short hb[4], lb[4];
#pragma unroll
    for (int j = 0; j < 4; j++) {
        __nv_bfloat16 h = __float2bfloat16(f[j]);
        __nv_bfloat16 l = __float2bfloat16(f[j] - __bfloat162float(h));
        hb[j] = __bfloat16_as_ushort(h);
        lb[j] = __bfloat16_as_ushort(l);
    }
    hi[i] = make_uint2((uint32_t)hb[0] | ((uint32_t)hb[1] << 16),
                       (uint32_t)hb[2] | ((uint32_t)hb[3] << 16));
    lo[i] = make_uint2((uint32_t)lb[0] | ((uint32_t)lb[1] << 16),
                       (uint32_t)lb[2] | ((uint32_t)lb[3] << 16));
}

// 4 weights fused: W[k][n] -> Th[n][k], Tl[n][k] bf16 (z = which weight)
__global__ void transpose_split4_kernel(const float* __restrict__ W0,
                                        const float* __restrict__ W1,
                                        const float* __restrict__ W2,
                                        const float* __restrict__ W3,
                                        __nv_bfloat16* __restrict__ Th,
                                        __nv_bfloat16* __restrict__ Tl)
{
    const float* W = (blockIdx.z == 0) ? W0 : (blockIdx.z == 1) ? W1
                   : (blockIdx.z == 2) ? W2 : W3;
    Th += (size_t)blockIdx.z * EMB * EMB;
    Tl += (size_t)blockIdx.z * EMB * EMB;
    __shared__ float t[32][33];
    int nx = blockIdx.x * 32, ky = blockIdx.y * 32;
    int tx = threadIdx.x, ty = threadIdx.y;
#pragma unroll
    for (int i = 0; i < 32; i += 8)
        t[ty + i][tx] = W[(size_t)(ky + ty + i) * EMB + nx + tx];
    __syncthreads();
#pragma unroll
    for (int i = 0; i < 32; i += 8) {
        float v = t[tx][ty + i];
        __nv_bfloat16 h = __float2bfloat16(v);
        __nv_bfloat16 l = __float2bfloat16(v - __bfloat162float(h));
        size_t o = (size_t)(nx + ty + i) * EMB + ky + tx;
        Th[o] = h;
        Tl[o] = l;
    }
}

// ======================= mma.sync GEMM =====================================
// CTA tile 128x128, BK=64, 8 warps (warp tile 64x32), cp.async double buffer.
// Output: fp32 (Cf != null) or bf16 hi/lo split (Ch/Cl).
constexpr int GSM_A0 = 0;
constexpr int GSM_B0 = 16384;
constexpr int GSM_A1 = 32768;
constexpr int GSM_B1 = 49152;
constexpr int GSM_TOTAL = 65536;

__device__ __forceinline__ void gemm_issue_chunk(
    const __nv_bfloat16* __restrict__ Asrc,
    const __nv_bfloat16* __restrict__ Bsrc,
    uint32_t smem_base, uint32_t offA, uint32_t offB, int tid)
{
#pragma unroll
    for (int i = 0; i < 4; i++) {
        int cidx = tid + 256 * i;
        int r  = cidx >> 3;
        int cb = cidx & 7;
        uint32_t sw = SMEM_SWIZZLE_128B((uint32_t)(r * 128 + cb * 16));
        cp_async16(smem_base + offA + sw, Asrc + (size_t)r * EMB + cb * 8);
        cp_async16(smem_base + offB + sw, Bsrc + (size_t)r * EMB + cb * 8);
    }
    cp_commit();
}

__global__ void __launch_bounds__(256, 2)
tc_gemm_kernel(const __nv_bfloat16* __restrict__ Ah,
               const __nv_bfloat16* __restrict__ Al,
               const __nv_bfloat16* __restrict__ Bh,
               const __nv_bfloat16* __restrict__ Bl,
               const float* __restrict__ bias,
               float* __restrict__ Cf,
               __nv_bfloat16* __restrict__ Ch,
               __nv_bfloat16* __restrict__ Cl)
{
    extern __shared__ char smem[];
    const uint32_t smem_base = smem_to_u32(smem);
    const int tid  = threadIdx.x;
    const int w    = tid >> 5;
    const int lane = tid & 31;
    const int n0 = blockIdx.x * 128;
    const int m0 = blockIdx.y * 128;

    const int wm = (w & 1) * 64;
    const int wn = (w >> 1) * 32;

    const __nv_bfloat16* Ap[3] = {Ah, Ah, Al};
    const __nv_bfloat16* Bp[3] = {Bh, Bl, Bh};
    const uint32_t offA[2] = {GSM_A0, GSM_A1};
    const uint32_t offB[2] = {GSM_B0, GSM_B1};

    float acc[4][4][4];
#pragma unroll
    for (int i = 0; i < 4; i++)
#pragma unroll
        for (int j = 0; j < 4; j++)
#pragma unroll
            for (int k = 0; k < 4; k++) acc[i][j][k] = 0.f;

    const uint32_t aRowOff =
        (uint32_t)((wm + (lane & 15)) * 128) + (uint32_t)((lane >> 4) * 16);
    const uint32_t bRowOff =
        (uint32_t)((wn + ((lane >> 4) << 3) + (lane & 7)) * 128) +
        (uint32_t)(((lane >> 3) & 1) * 16);

    gemm_issue_chunk(Ap[0] + (size_t)m0 * EMB, Bp[0] + (size_t)n0 * EMB,
                     smem_base, offA[0], offB[0], tid);

    for (int c = 0; c < 48; c++) {
        const int buf = c & 1;
        if (c + 1 < 48) {
            const int pass = (c + 1) >> 4;
            const int kc   = ((c + 1) & 15) * 64;
            gemm_issue_chunk(Ap[pass] + (size_t)m0 * EMB + kc,
                             Bp[pass] + (size_t)n0 * EMB + kc,
                             smem_base, offA[buf ^ 1], offB[buf ^ 1], tid);
            cp_wait1();
        } else {
            cp_wait0();
        }
        __syncthreads();

        const uint32_t abase = smem_base + offA[buf];
        const uint32_t bbase = smem_base + offB[buf];
#pragma unroll
        for (int ks = 0; ks < 4; ks++) {
            const uint32_t kb = ks * 32;
            uint32_t bfrag[4][2];
#pragma unroll
            for (int p = 0; p < 2; p++) {
                uint32_t off = bRowOff + p * 2048 + kb;
                uint32_t sw  = SMEM_SWIZZLE_128B(off);
                ldsm_x4(bfrag[2 * p][0], bfrag[2 * p][1],
                        bfrag[2 * p + 1][0], bfrag[2 * p + 1][1], bbase + sw);
            }
            uint32_t afrag[4][4];
#pragma unroll
            for (int mt = 0; mt < 4; mt++) {
                uint32_t off = aRowOff + mt * 2048 + kb;
                uint32_t sw  = SMEM_SWIZZLE_128B(off);
                ldsm_x4(afrag[mt][0], afrag[mt][1], afrag[mt][2], afrag[mt][3],
                        abase + sw);
            }
#pragma unroll
            for (int mt = 0; mt < 4; mt++)
#pragma unroll
                for (int nt = 0; nt < 4; nt++)
                    mma_bf16(acc[mt][nt], afrag[mt], bfrag[nt]);
        }
        __syncthreads();
    }

    const int rbase = m0 + wm + (lane >> 2);
    const int cbase = n0 + wn + (lane & 3) * 2;
#pragma unroll
    for (int mt = 0; mt < 4; mt++) {
#pragma unroll
        for (int nt = 0; nt < 4; nt++) {
            const int r = rbase + mt * 16;
            const int cc = cbase + nt * 8;
            float2 b2 = *(const float2*)(bias + cc);
            float v00 = acc[mt][nt][0] + b2.x;
            float v01 = acc[mt][nt][1] + b2.y;
            float v10 = acc[mt][nt][2] + b2.x;
            float v11 = acc[mt][nt][3] + b2.y;
            if (Cf) {
                *(float2*)(Cf + (size_t)r * EMB + cc)       = make_float2(v00, v01);
                *(float2*)(Cf + (size_t)(r + 8) * EMB + cc) = make_float2(v10, v11);
            } else {
                __nv_bfloat16 h00 = __float2bfloat16(v00);
                __nv_bfloat16 h01 = __float2bfloat16(v01);
                __nv_bfloat16 h10 = __float2bfloat16(v10);
                __nv_bfloat16 h11 = __float2bfloat16(v11);
                __nv_bfloat16 l00 = __float2bfloat16(v00 - __bfloat162float(h00));
                __nv_bfloat16 l01 = __float2bfloat16(v01 - __bfloat162float(h01));
                __nv_bfloat16 l10 = __float2bfloat16(v10 - __bfloat162float(h10));
                __nv_bfloat16 l11 = __float2bfloat16(v11 - __bfloat162float(h11));
                *(uint32_t*)(Ch + (size_t)r * EMB + cc)       = pack_bf16x2(h00, h01);
                *(uint32_t*)(Ch + (size_t)(r + 8) * EMB + cc) = pack_bf16x2(h10, h11);
                *(uint32_t*)(Cl + (size_t)r * EMB + cc)       = pack_bf16x2(l00, l01);
                *(uint32_t*)(Cl + (size_t)(r + 8) * EMB + cc) = pack_bf16x2(l10, l11);
            }
        }
    }
}

// ======================= tensor-core banded attention ======================
// One CTA per (b, h, 64-query tile). 256 threads / 8 warps.
// S = Q K^T over 5 key chunks of 64 (3-term split), masked+scaled -> Ss smem.
// Softmax (4 thr/row), P -> bf16 hi/lo, then O = P V (3-term split).
constexpr int A_QH = 0;
constexpr int A_QL = 8192;
constexpr int A_KH = 16384;
constexpr int A_KL = 24576;
constexpr int A_VH = 32768;       // transposed V chunk [d][key]
constexpr int A_VL = 40960;
constexpr int A_SS = 49152;                       // 64 x 328 fp32
constexpr int A_PH = A_SS + 64 * 328 * 4;         // 133120, 64 x 328 bf16
constexpr int A_PL = A_PH + 64 * 328 * 2;         // 175104
constexpr int A_RS = A_PL + 64 * 328 * 2;         // 217088
constexpr int A_TOTAL = A_RS + 256;               // 217344 bytes
constexpr int PSTRIDE = 328;                      // elems per P/S row

__global__ void __launch_bounds__(256, 1)
attn_tc_kernel(const __nv_bfloat16* __restrict__ Qh,
               const __nv_bfloat16* __restrict__ Ql,
               const __nv_bfloat16* __restrict__ Kh,
               const __nv_bfloat16* __restrict__ Kl,
               const __nv_bfloat16* __restrict__ Vh,
               const __nv_bfloat16* __restrict__ Vl,
               __nv_bfloat16* __restrict__ Ah,
               __nv_bfloat16* __restrict__ Al)
{
    extern __shared__ char smem[];
    const uint32_t sb = smem_to_u32(smem);
    const int tid  = threadIdx.x;
    const int w    = tid >> 5;
    const int lane = tid & 31;
    const int q0 = blockIdx.x * QT;
    const int bh = blockIdx.y;
    const int b  = bh >> 4;
    const int h  = bh & 15;
    const size_t gbase = ((size_t)b * S_LEN) * EMB + (size_t)h * 64;
    const float inv_scale = 0.03125f;  // 1/sqrt(1024)

    // warp layout: 4 warps along m (16 rows each), 2 along n (32 each)
    const int wm = (w & 3) * 16;
    const int wn = (w >> 2) * 32;
    const uint32_t aRowOff =
        (uint32_t)((wm + (lane & 15)) * 128) + (uint32_t)((lane >> 4) * 16);
    const uint32_t bRowOff =
        (uint32_t)((wn + ((lane >> 4) << 3) + (lane & 7)) * 128) +
        (uint32_t)(((lane >> 3) & 1) * 16);

    // ---- load Q tile (hi/lo), 64 rows x 128B, swizzled ----
#pragma unroll
    for (int i = tid; i < 512; i += 256) {
        int r = i >> 3, cb = i & 7;
        uint32_t sw = SMEM_SWIZZLE_128B((uint32_t)(r * 128 + cb * 16));
        const size_t go = gbase + (size_t)(q0 + r) * EMB + cb * 8;
        cp_async16(sb + A_QH + sw, Qh + go);
        cp_async16(sb + A_QL + sw, Ql + go);
    }
    cp_commit();

    // ---- phase 1: S chunks ----
    for (int c = 0; c < 5; c++) {
        const int k0c = q0 - 128 + c * 64;
        // load K chunk (hi/lo) with row clipping
#pragma unroll
        for (int i = tid; i < 512; i += 256) {
            int r = i >> 3, cb = i & 7;
            int kk = k0c + r;
            uint32_t sw = SMEM_SWIZZLE_128B((uint32_t)(r * 128 + cb * 16));
            if (kk >= 0 && kk < S_LEN) {
                const size_t go = gbase + (size_t)kk * EMB + cb * 8;
                cp_async16(sb + A_KH + sw, Kh + go);
                cp_async16(sb + A_KL + sw, Kl + go);
            } else {
                asm volatile("st.shared.v4.b32 [%0], {%1,%1,%1,%1};"
                             :: "r"(sb + A_KH + sw), "r"(0) : "memory");
                asm volatile("st.shared.v4.b32 [%0], {%1,%1,%1,%1};"
                             :: "r"(sb + A_KL + sw), "r"(0) : "memory");
            }
        }
        cp_commit();
        cp_wait0();
        __syncthreads();

        float acc[4][4];
#pragma unroll
        for (int j = 0; j < 4; j++)
#pragma unroll
            for (int k = 0; k < 4; k++) acc[j][k] = 0.f;

        const uint32_t abases[3] = {sb + A_QH, sb + A_QH, sb + A_QL};
        const uint32_t bbases[3] = {sb + A_KH, sb + A_KL, sb + A_KH};
#pragma unroll
        for (int pass = 0; pass < 3; pass++) {
#pragma unroll
            for (int ks = 0; ks < 4; ks++) {
                const uint32_t kb = ks * 32;
                uint32_t afrag[4];
                ldsm_x4(afrag[0], afrag[1], afrag[2], afrag[3],
                        abases[pass] + SMEM_SWIZZLE_128B(aRowOff + kb));
                uint32_t bfrag[4][2];
#pragma unroll
                for (int p = 0; p < 2; p++) {
                    uint32_t sw = SMEM_SWIZZLE_128B(bRowOff + p * 2048 + kb);
                    ldsm_x4(bfrag[2 * p][0], bfrag[2 * p][1],
                            bfrag[2 * p + 1][0], bfrag[2 * p + 1][1],
                            bbases[pass] + sw);
                }
#pragma unroll
                for (int nt = 0; nt < 4; nt++)
                    mma_bf16(acc[nt], afrag, bfrag[nt]);
            }
        }

        // epilogue: mask + scale -> Ss
        float* Ss = (float*)(smem + A_SS);
        const int r0 = wm + (lane >> 2);
        const int c0 = wn + (lane & 3) * 2;
#pragma unroll
        for (int nt = 0; nt < 4; nt++) {
            const int col = c0 + nt * 8;
#pragma unroll
            for (int half = 0; half < 2; half++) {
                const int row = r0 + half * 8;
                const int qi = q0 + row;
#pragma unroll
                for (int e = 0; e < 2; e++) {
                    const int kj = k0c + col + e;
                    const int diff = kj - qi;
                    bool ok = (kj >= 0) && (kj < S_LEN) &&
                              (diff <= 128) && (diff >= -128);
                    float v = acc[nt][half * 2 + e];
                    Ss[row * PSTRIDE + c * 64 + col + e] =
                        ok ? v * inv_scale : -1e30f;
                }
            }
        }
        __syncthreads();   // mma done + Ss written; safe to overwrite K
    }

    // ---- phase 2: softmax + P -> bf16 hi/lo (fused) ----
    {
        const int row = tid >> 2;
        const int l   = tid & 3;
        float* Srow = (float*)(smem + A_SS) + row * PSTRIDE;
        __nv_bfloat16* Phrow = (__nv_bfloat16*)(smem + A_PH) + row * PSTRIDE;
        __nv_bfloat16* Plrow = (__nv_bfloat16*)(smem + A_PL) + row * PSTRIDE;
        float m = -1e30f;
        for (int cc = l; cc < KWIN; cc += 4) m = fmaxf(m, Srow[cc]);
        m = fmaxf(m, __shfl_xor_sync(0xFFFFFFFF, m, 1));
        m = fmaxf(m, __shfl_xor_sync(0xFFFFFFFF, m, 2));
        float s = 0.f;
        for (int cc = l; cc < KWIN; cc += 4) {
            float p = __expf(Srow[cc] - m);
            s += p;
            __nv_bfloat16 ph = __float2bfloat16(p);
            Phrow[cc] = ph;
            Plrow[cc] = __float2bfloat16(p - __bfloat162float(ph));
        }
        s += __shfl_xor_sync(0xFFFFFFFF, s, 1);
        s += __shfl_xor_sync(0xFFFFFFFF, s, 2);
        if (l == 0) *((float*)(smem + A_RS) + row) = s;
    }

    // ---- phase 3: O = P V over 5 chunks ----
    float oacc[4][4];
#pragma unroll
    for (int j = 0; j < 4; j++)
#pragma unroll
        for (int k = 0; k < 4; k++) oacc[j][k] = 0.f;

    // A operand (P) row stride 656 bytes, no swizzle
    const uint32_t pRowOff =
        (uint32_t)((wm + (lane & 15)) * (PSTRIDE * 2)) +
        (uint32_t)((lane >> 4) * 16);

    for (int c = 0; c < 5; c++) {
        const int k0c = q0 - 128 + c * 64;
        __syncthreads();   // previous chunk's ldsm done before overwrite
        // load V chunk transposed: Vt[d][key], 128B rows, swizzled (16B-granular)
#pragma unroll
        for (int i = tid; i < 512; i += 256) {
            int r = i >> 3, cb = i & 7;
            int kk = k0c + r;
            uint4 vh = make_uint4(0, 0, 0, 0), vl = make_uint4(0, 0, 0, 0);
            if (kk >= 0 && kk < S_LEN) {
                const size_t go = gbase + (size_t)kk * EMB + cb * 8;
                vh = *(const uint4*)(Vh + go);
                vl = *(const uint4*)(Vl + go);
            }
            const unsigned short* hs = (const unsigned short*)&vh;
            const unsigned short* ls = (const unsigned short*)&vl;
            const uint32_t intra = (uint32_t)((r & 7) * 2);
            const uint32_t chunk16 = (uint32_t)((r >> 3) * 16);
#pragma unroll
            for (int j = 0; j < 8; j++) {
                const int d = cb * 8 + j;
                uint32_t base =
                    SMEM_SWIZZLE_128B((uint32_t)(d * 128) + chunk16) + intra;
                *(unsigned short*)(smem + A_VH + base) = hs[j];
                *(unsigned short*)(smem + A_VL + base) = ls[j];
            }
        }
        __syncthreads();

        const uint32_t pab[3] = {sb + A_PH, sb + A_PL, sb + A_PH};
        const uint32_t vbb[3] = {sb + A_VH, sb + A_VH, sb + A_VL};
#pragma unroll
        for (int pass = 0; pass < 3; pass++) {
#pragma unroll
            for (int ks = 0; ks < 4; ks++) {
                uint32_t afrag[4];
                ldsm_x4(afrag[0], afrag[1], afrag[2], afrag[3],
                        pab[pass] + pRowOff + (uint32_t)(c * 128 + ks * 32));
                uint32_t bfrag[4][2];
#pragma unroll
                for (int p = 0; p < 2; p++) {
                    uint32_t sw = SMEM_SWIZZLE_128B(bRowOff + p * 2048 + ks * 32);
                    ldsm_x4(bfrag[2 * p][0], bfrag[2 * p][1],
                            bfrag[2 * p + 1][0], bfrag[2 * p + 1][1],
                            vbb[pass] + sw);
                }
#pragma unroll
                for (int nt = 0; nt < 4; nt++)
                    mma_bf16(oacc[nt], afrag, bfrag[nt]);
            }
        }
    }

    // ---- epilogue: normalize, split to bf16 hi/lo, store ----
    {
        const int r0 = wm + (lane >> 2);
        const int c0 = wn + (lane & 3) * 2;
        const float* rs = (const float*)(smem + A_RS);
#pragma unroll
        for (int half = 0; half < 2; half++) {
            const int row = r0 + half * 8;
            const float rinv = 1.0f / rs[row];
            const size_t go = gbase + (size_t)(q0 + row) * EMB;
#pragma unroll
            for (int nt = 0; nt < 4; nt++) {
                const int col = c0 + nt * 8;
                float v0 = oacc[nt][half * 2 + 0] * rinv;
                float v1 = oacc[nt][half * 2 + 1] * rinv;
                __nv_bfloat16 h0 = __float2bfloat16(v0);
                __nv_bfloat16 h1 = __float2bfloat16(v1);
                __nv_bfloat16 l0 = __float2bfloat16(v0 - __bfloat162float(h0));
                __nv_bfloat16 l1 = __float2bfloat16(v1 - __bfloat162float(h1));
                *(uint32_t*)(Ah + go + col) = pack_bf16x2(h0, h1);
                *(uint32_t*)(Al + go + col) = pack_bf16x2(l0, l1);
            }
        }
    }
}

// ===========================================================================
extern "C" void kernel_launch(void* const* d_in, const int* in_sizes, int n_in,
                              void* d_out, int out_size)
{
    const float* x  = (const float*)d_in[0];
    const float* Wq = (const float*)d_in[1];
    const float* bq = (const float*)d_in[2];
    const float* Wk = (const float*)d_in[3];
    const float* bk = (const float*)d_in[4];
    const float* Wv = (const float*)d_in[5];
    const float* bv = (const float*)d_in[6];
    const float* Wo = (const float*)d_in[7];
    const float* bo = (const float*)d_in[8];
    float* out = (float*)d_out;

    __nv_bfloat16 *pXh, *pXl, *pQh, *pQl, *pKh, *pKl, *pVh, *pVl,
                  *pAh, *pAl, *pWth, *pWtl;
    cudaGetSymbolAddress((void**)&pXh, g_Xhi);
    cudaGetSymbolAddress((void**)&pXl, g_Xlo);
    cudaGetSymbolAddress((void**)&pQh, g_Qhi);
    cudaGetSymbolAddress((void**)&pQl, g_Qlo);
    cudaGetSymbolAddress((void**)&pKh, g_Khi);
    cudaGetSymbolAddress((void**)&pKl, g_Klo);
    cudaGetSymbolAddress((void**)&pVh, g_Vhi);
    cudaGetSymbolAddress((void**)&pVl, g_Vlo);
    cudaGetSymbolAddress((void**)&pAh, g_Ahi);
    cudaGetSymbolAddress((void**)&pAl, g_Alo);
    cudaGetSymbolAddress((void**)&pWth, g_Wth);
    cudaGetSymbolAddress((void**)&pWtl, g_Wtl);

    cudaFuncSetAttribute(tc_gemm_kernel,
                         cudaFuncAttributeMaxDynamicSharedMemorySize, GSM_TOTAL);
    cudaFuncSetAttribute(attn_tc_kernel,
                         cudaFuncAttributeMaxDynamicSharedMemorySize, A_TOTAL);

    const int n4 = MTOT * EMB / 4;
    split_kernel<<<(n4 + 255) / 256, 256>>>((const float4*)x,
                                            (uint2*)pXh, (uint2*)pXl, n4);
    dim3 tgrid(EMB / 32, EMB / 32, 4);
    dim3 tblk(32, 8);
    transpose_split4_kernel<<<tgrid, tblk>>>(Wq, Wk, Wv, Wo, pWth, pWtl);

    dim3 ggrid(EMB / 128, MTOT / 128);   // (8, 32)
    tc_gemm_kernel<<<ggrid, 256, GSM_TOTAL>>>(pXh, pXl,
        pWth + 0ull * EMB * EMB, pWtl + 0ull * EMB * EMB, bq,
        nullptr, pQh, pQl);
    tc_gemm_kernel<<<ggrid, 256, GSM_TOTAL>>>(pXh, pXl,
        pWth + 1ull * EMB * EMB, pWtl + 1ull * EMB * EMB, bk,
        nullptr, pKh, pKl);
    tc_gemm_kernel<<<ggrid, 256, GSM_TOTAL>>>(pXh, pXl,
        pWth + 2ull * EMB * EMB, pWtl + 2ull * EMB * EMB, bv,
        nullptr, pVh, pVl);

    dim3 agrid(S_LEN / QT, BATCH * 16);  // (32, 32)
    attn_tc_kernel<<<agrid, 256, A_TOTAL>>>(pQh, pQl, pKh, pKl, pVh, pVl,
                                            pAh, pAl);

    tc_gemm_kernel<<<ggrid, 256, GSM_TOTAL>>>(pAh, pAl,
        pWth + 3ull * EMB * EMB, pWtl + 3ull * EMB * EMB, bo,
        out, nullptr, nullptr);
}